// round 1
// baseline (speedup 1.0000x reference)
#include <cuda_runtime.h>
#include <stdint.h>

#define VOCAB 100000
#define EMBED 64
#define KIDS  20
#define BROWS (1024 * 50)   // B*S output rows

// Scratch: W transposed to [V, E] so each vocab row is a contiguous 256B chunk.
// 100000 * 64 * 4 B = 25.6 MB (fits in 126 MB L2).
__device__ float4 g_Wt[VOCAB * EMBED / 4];

// ---------------------------------------------------------------------------
// Kernel 1: tiled transpose W[E, V] -> Wt[V, E]
// Grid: (V/32, E/32), block (32, 8). Classic smem tile with +1 pad.
// ---------------------------------------------------------------------------
__global__ void transpose_W_kernel(const float* __restrict__ W) {
    __shared__ float tile[32][33];
    const int v0 = blockIdx.x * 32;
    const int e0 = blockIdx.y * 32;
    const int tx = threadIdx.x;   // 0..31
    const int ty = threadIdx.y;   // 0..7

    // Coalesced read along V: W[e0+ty+8j][v0+tx]
    #pragma unroll
    for (int j = 0; j < 4; j++) {
        tile[ty + 8 * j][tx] =
            W[(size_t)(e0 + ty + 8 * j) * VOCAB + (v0 + tx)];
    }
    __syncthreads();

    // Coalesced write along E: Wt[v0+ty+8j][e0+tx]
    float* Wt = reinterpret_cast<float*>(g_Wt);
    #pragma unroll
    for (int j = 0; j < 4; j++) {
        Wt[(size_t)(v0 + ty + 8 * j) * EMBED + (e0 + tx)] = tile[tx][ty + 8 * j];
    }
}

// ---------------------------------------------------------------------------
// Kernel 2: gather-reduce. 16 lanes per output row; lane t owns e in [4t,4t+4).
// acc = bias4[t] + sum_k Wt4[ids[row][k]*16 + t]
// 256 threads/block = 16 rows/block -> 3200 blocks.
// ---------------------------------------------------------------------------
__global__ __launch_bounds__(256)
void gather_reduce_kernel(const int* __restrict__ ids,
                          const float* __restrict__ bias,
                          float* __restrict__ out) {
    const int gtid = blockIdx.x * blockDim.x + threadIdx.x;
    const int row  = gtid >> 4;      // one row per 16 lanes
    const int lane = gtid & 15;
    if (row >= BROWS) return;

    const int* idp = ids + (size_t)row * KIDS;

    float4 acc = reinterpret_cast<const float4*>(bias)[lane];

    // Prefetch all 20 ids first to maximize MLP on the float4 gathers.
    int id[KIDS];
    #pragma unroll
    for (int k = 0; k < KIDS; k++) id[k] = __ldg(idp + k);

    #pragma unroll
    for (int k = 0; k < KIDS; k++) {
        const float4 w = __ldg(&g_Wt[(size_t)id[k] * 16 + lane]);
        acc.x += w.x; acc.y += w.y; acc.z += w.z; acc.w += w.w;
    }

    reinterpret_cast<float4*>(out)[(size_t)row * 16 + lane] = acc;
}

// ---------------------------------------------------------------------------
// Launch: inputs in metadata order: content_input (int32), W (f32), b (f32)
// ---------------------------------------------------------------------------
extern "C" void kernel_launch(void* const* d_in, const int* in_sizes, int n_in,
                              void* d_out, int out_size) {
    const int*   ids  = (const int*)  d_in[0];   // [B, S, K] int32
    const float* W    = (const float*)d_in[1];   // [E, V] f32
    const float* bias = (const float*)d_in[2];   // [E] f32
    float*       out  = (float*)d_out;           // [B, S, E] f32

    dim3 tgrid(VOCAB / 32, EMBED / 32);
    dim3 tblk(32, 8);
    transpose_W_kernel<<<tgrid, tblk>>>(W);

    const int threads = 256;
    const int rows_per_block = threads / 16;
    const int blocks = (BROWS + rows_per_block - 1) / rows_per_block;
    gather_reduce_kernel<<<blocks, threads>>>(ids, bias, out);
}